// round 9
// baseline (speedup 1.0000x reference)
#include <cuda_runtime.h>
#include <cstdint>
#include <math.h>

#define D_   1024
#define H_   16
#define HD_  64
#define FF_  4096
#define S_   1024
#define N_   2
#define L_   4096
#define ML   (L_*N_)
#define MS   (S_*N_)

// ---------------- scratch ----------------
__device__ float g_q[(size_t)ML*D_];
__device__ float g_k[(size_t)MS*D_];
__device__ float g_v[(size_t)MS*D_];
__device__ float g_attn[(size_t)ML*D_];
__device__ float g_tmp[(size_t)ML*D_];
__device__ float g_x[(size_t)ML*D_];
__device__ float g_ff[(size_t)ML*FF_];
__device__ float g_tgt[(size_t)ML*D_];
__device__ float g_M[(size_t)N_*H_*L_];
__device__ float g_Z[(size_t)N_*H_*L_];
__device__ float g_noise[2*N_*H_*HD_];
__device__ float g_wtf[25165824];   // tf32-rounded weights: qkv|out|ff1|ff2

// ---------------- threefry2x32 ----------------
__device__ __forceinline__ uint32_t rotl32(uint32_t x, int r) {
    return (x << r) | (x >> (32 - r));
}
__device__ __forceinline__ void threefry2x32(uint32_t k0, uint32_t k1,
                                             uint32_t x0, uint32_t x1,
                                             uint32_t& o0, uint32_t& o1) {
    uint32_t ks[3] = {k0, k1, k0 ^ k1 ^ 0x1BD11BDAu};
    const int rot[2][4] = {{13, 15, 26, 6}, {17, 29, 16, 24}};
    x0 += ks[0]; x1 += ks[1];
#pragma unroll
    for (int g = 0; g < 5; g++) {
        const int* r = rot[g & 1];
#pragma unroll
        for (int j = 0; j < 4; j++) {
            x0 += x1; x1 = rotl32(x1, r[j]); x1 ^= x0;
        }
        x0 += ks[(g + 1) % 3];
        x1 += ks[(g + 2) % 3] + (uint32_t)(g + 1);
    }
    o0 = x0; o1 = x1;
}

__global__ void noise_kernel(float* __restrict__ noise) {
    int t = blockIdx.x * blockDim.x + threadIdx.x;
    if (t >= 2 * 2048) return;
    int layer = t >> 11;
    int idx = t & 2047;
    uint32_t ka, kb;
    threefry2x32(0u, 42u, 0u, (uint32_t)layer, ka, kb);
    uint32_t o0, o1;
    threefry2x32(ka, kb, 0u, (uint32_t)idx, o0, o1);
    uint32_t bits = o0 ^ o1;
    uint32_t fb = (bits >> 9) | 0x3f800000u;
    float f = __uint_as_float(fb) - 1.0f;
    const float lo = -0.99999994f;
    float u = fmaf(f, 2.0f, lo);
    u = fmaxf(u, lo);
    noise[t] = 1.41421356237309515f * erfinvf(u);
}

// ---------------- tf32 / mma helpers ----------------
__device__ __forceinline__ uint32_t tf32bits(float x) {
    float y;
    asm("cvt.rna.tf32.f32 %0, %1;" : "=f"(y) : "f"(x));
    return __float_as_uint(y);
}
__device__ __forceinline__ float tf32round(float x) {
    float y;
    asm("cvt.rna.tf32.f32 %0, %1;" : "=f"(y) : "f"(x));
    return y;
}
__device__ __forceinline__ void mma_tf32(float* c, const uint32_t* a, const uint32_t* b) {
    asm volatile(
        "mma.sync.aligned.m16n8k8.row.col.f32.tf32.tf32.f32 "
        "{%0,%1,%2,%3}, {%4,%5,%6,%7}, {%8,%9}, {%0,%1,%2,%3};"
        : "+f"(c[0]), "+f"(c[1]), "+f"(c[2]), "+f"(c[3])
        : "r"(a[0]), "r"(a[1]), "r"(a[2]), "r"(a[3]), "r"(b[0]), "r"(b[1]));
}
__device__ __forceinline__ void cp16(uint32_t dst, const void* src) {
    asm volatile("cp.async.cg.shared.global [%0], [%1], 16;" :: "r"(dst), "l"(src));
}

// weight tf32 pre-rounding
__global__ void wcvt_kernel(const float* __restrict__ src, float* __restrict__ dst, int n4) {
    int i = blockIdx.x * blockDim.x + threadIdx.x;
    if (i >= n4) return;
    float4 v = *(const float4*)(src + (size_t)i * 4);
    v.x = tf32round(v.x); v.y = tf32round(v.y);
    v.z = tf32round(v.z); v.w = tf32round(v.w);
    *(float4*)(dst + (size_t)i * 4) = v;
}

// ---------------- TF32 GEMM core, 3-stage cp.async, BK=32 ----------------
#define GPAD 36
#define GSTG (128*GPAD)
#define TGEMM_SMEM (6*GSTG*4)

template<bool RELU, bool RES, bool ACVT, bool OCVT>
__device__ __forceinline__ void tgemm_core(
    const float* __restrict__ Ap, const float* __restrict__ Bp,
    const float* __restrict__ bias, float* __restrict__ C,
    const float* __restrict__ Res,
    int crow0, int ccol0, int Nn, int K, float postscale, float* smf) {
    const uint32_t smem_u32 = (uint32_t)__cvta_generic_to_shared(smf);
    const int tid = threadIdx.x;
    const int warp = tid >> 5, lane = tid & 31;
    const int g = lane >> 2, tig = lane & 3;
    const int wm = (warp >> 1) * 32;
    const int wn = (warp & 1) * 64;

    float acc[2][8][4];
#pragma unroll
    for (int mt = 0; mt < 2; mt++)
#pragma unroll
        for (int nt = 0; nt < 8; nt++)
#pragma unroll
            for (int j = 0; j < 4; j++) acc[mt][nt][j] = 0.f;

    auto load_stage = [&](int buf, int k0) {
#pragma unroll
        for (int u = 0; u < 4; u++) {
            int idx = tid + u * 256;
            int r = idx >> 3;
            int c = (idx & 7) << 2;
            cp16(smem_u32 + (uint32_t)((buf * GSTG + r * GPAD + c) << 2),
                 Ap + (size_t)r * K + k0 + c);
            cp16(smem_u32 + (uint32_t)(((3 + buf) * GSTG + r * GPAD + c) << 2),
                 Bp + (size_t)r * K + k0 + c);
        }
        asm volatile("cp.async.commit_group;");
    };

    auto acv = [](float x) -> uint32_t {
        return ACVT ? tf32bits(x) : __float_as_uint(x);
    };

    const int nb = K >> 5;
    load_stage(0, 0);
    if (nb > 1) load_stage(1, 32);

    for (int kb = 0; kb < nb; kb++) {
        if (kb + 1 < nb) asm volatile("cp.async.wait_group 1;");
        else             asm volatile("cp.async.wait_group 0;");
        __syncthreads();
        if (kb + 2 < nb) load_stage((kb + 2) % 3, (kb + 2) * 32);

        const float* As = smf + (kb % 3) * GSTG;
        const float* Bs = smf + (3 + kb % 3) * GSTG;

        uint32_t af[2][2][4], bf[2][8][2];
        auto frag_load = [&](int slot, int ks) {
            int kk = ks * 8 + tig;
#pragma unroll
            for (int mt = 0; mt < 2; mt++) {
                int col = wm + mt * 16 + g;
                af[slot][mt][0] = acv(As[col * GPAD + kk]);
                af[slot][mt][1] = acv(As[(col + 8) * GPAD + kk]);
                af[slot][mt][2] = acv(As[col * GPAD + kk + 4]);
                af[slot][mt][3] = acv(As[(col + 8) * GPAD + kk + 4]);
            }
#pragma unroll
            for (int nt = 0; nt < 8; nt++) {
                int coln = wn + nt * 8 + g;
                bf[slot][nt][0] = __float_as_uint(Bs[coln * GPAD + kk]);
                bf[slot][nt][1] = __float_as_uint(Bs[coln * GPAD + kk + 4]);
            }
        };

        frag_load(0, 0);
#pragma unroll
        for (int ks = 0; ks < 4; ks++) {
            const int cur = ks & 1;
            if (ks < 3) frag_load(cur ^ 1, ks + 1);
#pragma unroll
            for (int nt = 0; nt < 8; nt++) {
                mma_tf32(acc[0][nt], af[cur][0], bf[cur][nt]);
                mma_tf32(acc[1][nt], af[cur][1], bf[cur][nt]);
            }
        }
    }

#pragma unroll
    for (int mt = 0; mt < 2; mt++) {
        int r0 = crow0 + wm + mt * 16 + g;
        int r1 = r0 + 8;
#pragma unroll
        for (int nt = 0; nt < 8; nt++) {
            int cb = ccol0 + wn + nt * 8 + 2 * tig;
            float b0 = bias[cb], b1 = bias[cb + 1];
            float v00 = (acc[mt][nt][0] + b0) * postscale;
            float v01 = (acc[mt][nt][1] + b1) * postscale;
            float v10 = (acc[mt][nt][2] + b0) * postscale;
            float v11 = (acc[mt][nt][3] + b1) * postscale;
            if (RELU) {
                v00 = fmaxf(v00, 0.f); v01 = fmaxf(v01, 0.f);
                v10 = fmaxf(v10, 0.f); v11 = fmaxf(v11, 0.f);
            }
            size_t o0 = (size_t)r0 * Nn + cb;
            size_t o1 = (size_t)r1 * Nn + cb;
            if (RES) {
                float2 rA = *(const float2*)(Res + o0);
                float2 rB = *(const float2*)(Res + o1);
                v00 += rA.x; v01 += rA.y; v10 += rB.x; v11 += rB.y;
            }
            if (OCVT) {
                v00 = tf32round(v00); v01 = tf32round(v01);
                v10 = tf32round(v10); v11 = tf32round(v11);
            }
            *(float2*)(C + o0) = make_float2(v00, v01);
            *(float2*)(C + o1) = make_float2(v10, v11);
        }
    }
}

template<bool RELU, bool RES, bool ACVT, bool OCVT>
__global__ void __launch_bounds__(256) tgemm_kernel(
    const float* __restrict__ A, const float* __restrict__ B,
    const float* __restrict__ bias, float* __restrict__ C,
    const float* __restrict__ Res, int M, int Nn, int K, float postscale) {
    extern __shared__ float smf[];
    tgemm_core<RELU, RES, ACVT, OCVT>(A + (size_t)blockIdx.y * 128 * K,
                                      B + (size_t)blockIdx.x * 128 * K,
                                      bias, C, Res,
                                      blockIdx.y * 128, blockIdx.x * 128, Nn, K, postscale, smf);
}

// fused q/k/v projection: grid (8, 96); outputs tf32-rounded
__global__ void __launch_bounds__(256) qkv_kernel(
    const float* __restrict__ xin, const float* __restrict__ keyin,
    const float* __restrict__ valin, const float* __restrict__ W,
    const float* __restrict__ Bi,
    float* __restrict__ qb, float* __restrict__ kb, float* __restrict__ vb) {
    extern __shared__ float smf[];
    const int bm = blockIdx.y, bn = blockIdx.x;
    if (bm < 64) {
        tgemm_core<false, false, true, true>(xin + (size_t)bm * 128 * D_,
                                 W + (size_t)bn * 128 * D_, Bi, qb, nullptr,
                                 bm * 128, bn * 128, D_, D_, 0.125f, smf);
    } else if (bm < 80) {
        tgemm_core<false, false, true, true>(keyin + (size_t)(bm - 64) * 128 * D_,
                                 W + (size_t)(D_ + bn * 128) * D_, Bi + D_, kb, nullptr,
                                 (bm - 64) * 128, bn * 128, D_, D_, 1.f, smf);
    } else {
        tgemm_core<false, false, true, true>(valin + (size_t)(bm - 80) * 128 * D_,
                                 W + (size_t)(2 * D_ + bn * 128) * D_, Bi + 2 * D_, vb, nullptr,
                                 (bm - 80) * 128, bn * 128, D_, D_, 1.f, smf);
    }
}

// ---------------- tensor-core flash attention: 512 thr, 256-row Q tile ----------------
// k_s pad 68 (conflict-free QK B-frags), v_s pad 72 (conflict-free PV B-frags)
#define PPAD 68
#define KPK  68
#define KPV  72
#define QROWS 256
#define ATTN_SMEM ((QROWS*PPAD + 2*64*KPK + 2*64*KPV)*4)
__global__ void __launch_bounds__(512) attn_kernel(
    const float* __restrict__ Q, const float* __restrict__ Kb, const float* __restrict__ Vb,
    const float* __restrict__ noise, float* __restrict__ Out,
    float* __restrict__ Mb, float* __restrict__ Zb) {
    extern __shared__ uint32_t su[];
    uint32_t* p_s = su;                                    // QROWS*PPAD
    const uint32_t smem_u32 = (uint32_t)__cvta_generic_to_shared(su);
    const int n = blockIdx.z, h = blockIdx.y, l0 = blockIdx.x * QROWS;
    const int tid = threadIdx.x;
    const int warp = tid >> 5, lane = tid & 31;
    const int g = lane >> 2, tig = lane & 3;
    const int wm = warp * 16;

    auto kv_prefetch = [&](int buf, int s0) {
        uint32_t kbase = smem_u32 + (uint32_t)((QROWS * PPAD + buf * 64 * KPK) << 2);
        uint32_t vbase = smem_u32 + (uint32_t)((QROWS * PPAD + 2 * 64 * KPK + buf * 64 * KPV) << 2);
#pragma unroll
        for (int u = 0; u < 2; u++) {
            int t = tid + u * 512;
            int s = t >> 4, dc = (t & 15) << 2;
            size_t goff = ((size_t)(s0 + s) * N_ + n) * D_ + h * HD_ + dc;
            cp16(kbase + (uint32_t)((s * KPK + dc) << 2), Kb + goff);
            cp16(vbase + (uint32_t)((s * KPV + dc) << 2), Vb + goff);
        }
        asm volatile("cp.async.commit_group;");
    };

    kv_prefetch(0, 0);

    for (int t = tid; t < QROWS * 16; t += 512) {
        int r = t >> 4, dc = (t & 15) << 2;
        *(uint4*)(p_s + r * PPAD + dc) =
            *(const uint4*)(Q + ((size_t)(l0 + r) * N_ + n) * D_ + h * HD_ + dc);
    }
    __syncthreads();
    uint32_t qf[8][4];
#pragma unroll
    for (int ks = 0; ks < 8; ks++) {
        int kk = ks * 8 + tig;
        qf[ks][0] = p_s[(wm + g) * PPAD + kk];
        qf[ks][1] = p_s[(wm + g + 8) * PPAD + kk];
        qf[ks][2] = p_s[(wm + g) * PPAD + kk + 4];
        qf[ks][3] = p_s[(wm + g + 8) * PPAD + kk + 4];
    }

    float m0 = -1e30f, m1 = -1e30f, l0s = 0.f, l1s = 0.f;
    float acc_o[8][4];
#pragma unroll
    for (int nt = 0; nt < 8; nt++)
#pragma unroll
        for (int j = 0; j < 4; j++) acc_o[nt][j] = 0.f;

    for (int c = 0; c < 16; c++) {
        asm volatile("cp.async.wait_group 0;");
        __syncthreads();
        if (c + 1 < 16) kv_prefetch((c + 1) & 1, (c + 1) * 64);
        const uint32_t* k_s = su + QROWS * PPAD + (c & 1) * 64 * KPK;
        const uint32_t* v_s = su + QROWS * PPAD + 2 * 64 * KPK + (c & 1) * 64 * KPV;

        float acc_s[8][4];
#pragma unroll
        for (int nt = 0; nt < 8; nt++)
#pragma unroll
            for (int j = 0; j < 4; j++) acc_s[nt][j] = 0.f;
#pragma unroll
        for (int ks = 0; ks < 8; ks++) {
            int kk = ks * 8 + tig;
#pragma unroll
            for (int nt = 0; nt < 8; nt++) {
                uint32_t kf[2];
                kf[0] = k_s[(nt * 8 + g) * KPK + kk];
                kf[1] = k_s[(nt * 8 + g) * KPK + kk + 4];
                mma_tf32(acc_s[nt], qf[ks], kf);
            }
        }

        float cm0 = -1e30f, cm1 = -1e30f;
#pragma unroll
        for (int nt = 0; nt < 8; nt++) {
            cm0 = fmaxf(cm0, fmaxf(acc_s[nt][0], acc_s[nt][1]));
            cm1 = fmaxf(cm1, fmaxf(acc_s[nt][2], acc_s[nt][3]));
        }
        cm0 = fmaxf(cm0, __shfl_xor_sync(0xffffffffu, cm0, 1));
        cm0 = fmaxf(cm0, __shfl_xor_sync(0xffffffffu, cm0, 2));
        cm1 = fmaxf(cm1, __shfl_xor_sync(0xffffffffu, cm1, 1));
        cm1 = fmaxf(cm1, __shfl_xor_sync(0xffffffffu, cm1, 2));
        float mn0 = fmaxf(m0, cm0), mn1 = fmaxf(m1, cm1);
        float corr0 = __expf(m0 - mn0), corr1 = __expf(m1 - mn1);
        float rs0 = 0.f, rs1 = 0.f;
#pragma unroll
        for (int nt = 0; nt < 8; nt++) {
            float p00 = __expf(acc_s[nt][0] - mn0);
            float p01 = __expf(acc_s[nt][1] - mn0);
            float p10 = __expf(acc_s[nt][2] - mn1);
            float p11 = __expf(acc_s[nt][3] - mn1);
            rs0 += p00 + p01; rs1 += p10 + p11;
            uint2 a = make_uint2(tf32bits(p00), tf32bits(p01));
            uint2 b = make_uint2(tf32bits(p10), tf32bits(p11));
            *(uint2*)(p_s + (wm + g) * PPAD + nt * 8 + 2 * tig) = a;
            *(uint2*)(p_s + (wm + g + 8) * PPAD + nt * 8 + 2 * tig) = b;
        }
        rs0 += __shfl_xor_sync(0xffffffffu, rs0, 1);
        rs0 += __shfl_xor_sync(0xffffffffu, rs0, 2);
        rs1 += __shfl_xor_sync(0xffffffffu, rs1, 1);
        rs1 += __shfl_xor_sync(0xffffffffu, rs1, 2);
        l0s = l0s * corr0 + rs0;
        l1s = l1s * corr1 + rs1;
        m0 = mn0; m1 = mn1;
#pragma unroll
        for (int nt = 0; nt < 8; nt++) {
            acc_o[nt][0] *= corr0; acc_o[nt][1] *= corr0;
            acc_o[nt][2] *= corr1; acc_o[nt][3] *= corr1;
        }
        __syncwarp();

#pragma unroll
        for (int ks = 0; ks < 8; ks++) {
            int kk = ks * 8 + tig;
            uint32_t pf[4];
            pf[0] = p_s[(wm + g) * PPAD + kk];
            pf[1] = p_s[(wm + g + 8) * PPAD + kk];
            pf[2] = p_s[(wm + g) * PPAD + kk + 4];
            pf[3] = p_s[(wm + g + 8) * PPAD + kk + 4];
#pragma unroll
            for (int nt = 0; nt < 8; nt++) {
                uint32_t vf[2];
                vf[0] = v_s[kk * KPV + nt * 8 + g];
                vf[1] = v_s[(kk + 4) * KPV + nt * 8 + g];
                mma_tf32(acc_o[nt], pf, vf);
            }
        }
        __syncwarp();
    }

    {
        float mf0 = fmaxf(m0, 0.f), mf1 = fmaxf(m1, 0.f);
        float c0 = __expf(m0 - mf0), c1 = __expf(m1 - mf1);
        float pw0 = __expf(-mf0), pw1 = __expf(-mf1);
        float lf0 = l0s * c0 + pw0, lf1 = l1s * c1 + pw1;
        float inv0 = 1.f / lf0, inv1 = 1.f / lf1;
        int r0 = l0 + wm + g, r1 = r0 + 8;
        const float* nb = noise + (n * H_ + h) * HD_;
        float* o0p = Out + ((size_t)r0 * N_ + n) * D_ + h * HD_;
        float* o1p = Out + ((size_t)r1 * N_ + n) * D_ + h * HD_;
#pragma unroll
        for (int nt = 0; nt < 8; nt++) {
            int col = nt * 8 + 2 * tig;
            float nv0 = nb[col], nv1 = nb[col + 1];
            *(float2*)(o0p + col) = make_float2(
                tf32round((acc_o[nt][0] * c0 + pw0 * nv0) * inv0),
                tf32round((acc_o[nt][1] * c0 + pw0 * nv1) * inv0));
            *(float2*)(o1p + col) = make_float2(
                tf32round((acc_o[nt][2] * c1 + pw1 * nv0) * inv1),
                tf32round((acc_o[nt][3] * c1 + pw1 * nv1) * inv1));
        }
        if (tig == 0) {
            size_t base = (size_t)(n * H_ + h) * L_;
            Mb[base + r0] = mf0; Zb[base + r0] = lf0;
            Mb[base + r1] = mf1; Zb[base + r1] = lf1;
        }
    }
}

// ---------------- tensor-core attn_map (k_s pad 68 conflict fix) ----------------
#define AMQ 68
#define AMK 68
#define ATTNMAP_SMEM ((128*AMQ + 64*AMK)*4)
__global__ void __launch_bounds__(256) attnmap_kernel(
    const float* __restrict__ Q, const float* __restrict__ Kb,
    const float* __restrict__ Mb, const float* __restrict__ Zb,
    float* __restrict__ Out2) {
    extern __shared__ uint32_t su[];
    uint32_t* q_s = su;
    uint32_t* k_s = su + 128 * AMQ;
    const int n = blockIdx.z, l0 = blockIdx.x * 128, s0 = blockIdx.y * 64;
    const int tid = threadIdx.x;
    const int warp = tid >> 5, lane = tid & 31;
    const int g = lane >> 2, tig = lane & 3;
    const int wm = warp * 16;

    float acc[8][4];
#pragma unroll
    for (int nt = 0; nt < 8; nt++)
#pragma unroll
        for (int j = 0; j < 4; j++) acc[nt][j] = 0.f;

    for (int h = 0; h < H_; h++) {
        __syncthreads();
        for (int t = tid; t < 128 * 16; t += 256) {
            int r = t >> 4, dc = (t & 15) << 2;
            *(uint4*)(q_s + r * AMQ + dc) =
                *(const uint4*)(Q + ((size_t)(l0 + r) * N_ + n) * D_ + h * HD_ + dc);
        }
        for (int t = tid; t < 64 * 16; t += 256) {
            int s = t >> 4, dc = (t & 15) << 2;
            *(uint4*)(k_s + s * AMK + dc) =
                *(const uint4*)(Kb + ((size_t)(s0 + s) * N_ + n) * D_ + h * HD_ + dc);
        }
        __syncthreads();

        uint32_t qf[8][4];
#pragma unroll
        for (int ks = 0; ks < 8; ks++) {
            int kk = ks * 8 + tig;
            qf[ks][0] = q_s[(wm + g) * AMQ + kk];
            qf[ks][1] = q_s[(wm + g + 8) * AMQ + kk];
            qf[ks][2] = q_s[(wm + g) * AMQ + kk + 4];
            qf[ks][3] = q_s[(wm + g + 8) * AMQ + kk + 4];
        }
        float s_[8][4];
#pragma unroll
        for (int nt = 0; nt < 8; nt++)
#pragma unroll
            for (int j = 0; j < 4; j++) s_[nt][j] = 0.f;
#pragma unroll
        for (int ks = 0; ks < 8; ks++) {
            int kk = ks * 8 + tig;
#pragma unroll
            for (int nt = 0; nt < 8; nt++) {
                uint32_t kf[2];
                kf[0] = k_s[(nt * 8 + g) * AMK + kk];
                kf[1] = k_s[(nt * 8 + g) * AMK + kk + 4];
                mma_tf32(s_[nt], qf[ks], kf);
            }
        }

        size_t mz = (size_t)(n * H_ + h) * L_;
        int r0 = l0 + wm + g, r1 = r0 + 8;
        float mf0 = Mb[mz + r0], iz0 = 1.f / Zb[mz + r0];
        float mf1 = Mb[mz + r1], iz1 = 1.f / Zb[mz + r1];
#pragma unroll
        for (int nt = 0; nt < 8; nt++) {
            float w00 = __expf(s_[nt][0] - mf0) * iz0;
            float w01 = __expf(s_[nt][1] - mf0) * iz0;
            float w10 = __expf(s_[nt][2] - mf1) * iz1;
            float w11 = __expf(s_[nt][3] - mf1) * iz1;
            acc[nt][0] += __fdividef(1.f, 1.f + __expf(-w00));
            acc[nt][1] += __fdividef(1.f, 1.f + __expf(-w01));
            acc[nt][2] += __fdividef(1.f, 1.f + __expf(-w10));
            acc[nt][3] += __fdividef(1.f, 1.f + __expf(-w11));
        }
    }

    int r0 = l0 + wm + g, r1 = r0 + 8;
#pragma unroll
    for (int nt = 0; nt < 8; nt++) {
        int col = s0 + nt * 8 + 2 * tig;
        *(float2*)(Out2 + ((size_t)n * L_ + r0) * S_ + col) =
            make_float2(acc[nt][0] * (1.f / 16.f), acc[nt][1] * (1.f / 16.f));
        *(float2*)(Out2 + ((size_t)n * L_ + r1) * S_ + col) =
            make_float2(acc[nt][2] * (1.f / 16.f), acc[nt][3] * (1.f / 16.f));
    }
}

// ---------------- layernorm ----------------
__global__ void __launch_bounds__(256) ln_kernel(
    const float* __restrict__ X, const float* __restrict__ g,
    const float* __restrict__ b, float* __restrict__ Y) {
    const int row = blockIdx.x;
    const int tid = threadIdx.x;
    const float* x = X + (size_t)row * D_;
    float4 v = *(const float4*)(x + tid * 4);
    __shared__ float red[8];
    const int wid = tid >> 5, lane = tid & 31;

    float s = v.x + v.y + v.z + v.w;
#pragma unroll
    for (int o = 16; o; o >>= 1) s += __shfl_xor_sync(0xffffffffu, s, o);
    if (!lane) red[wid] = s;
    __syncthreads();
    float tot = 0.f;
#pragma unroll
    for (int w = 0; w < 8; w++) tot += red[w];
    float mean = tot * (1.f / D_);

    float dx = v.x - mean, dy = v.y - mean, dz = v.z - mean, dw = v.w - mean;
    float ss = dx * dx + dy * dy + dz * dz + dw * dw;
#pragma unroll
    for (int o = 16; o; o >>= 1) ss += __shfl_xor_sync(0xffffffffu, ss, o);
    __syncthreads();
    if (!lane) red[wid] = ss;
    __syncthreads();
    float tss = 0.f;
#pragma unroll
    for (int w = 0; w < 8; w++) tss += red[w];
    float inv = rsqrtf(tss * (1.f / D_) + 1e-5f);

    const int c = tid * 4;
    float4 gv = *(const float4*)(g + c);
    float4 bv = *(const float4*)(b + c);
    float4 o;
    o.x = dx * inv * gv.x + bv.x;
    o.y = dy * inv * gv.y + bv.y;
    o.z = dz * inv * gv.z + bv.z;
    o.w = dw * inv * gv.w + bv.w;
    *(float4*)(Y + (size_t)row * D_ + c) = o;
}

// ---------------- orchestration ----------------
extern "C" void kernel_launch(void* const* d_in, const int* in_sizes, int n_in,
                              void* d_out, int out_size) {
    const float* key_in   = (const float*)d_in[0];
    const float* value_in = (const float*)d_in[1];
    const float* query    = (const float*)d_in[2];
    const float* ipw      = (const float*)d_in[3];
    const float* ipb      = (const float*)d_in[4];
    const float* ow       = (const float*)d_in[5];
    const float* ob       = (const float*)d_in[6];
    const float* ln1g     = (const float*)d_in[7];
    const float* ln1b     = (const float*)d_in[8];
    const float* ln2g     = (const float*)d_in[9];
    const float* ln2b     = (const float*)d_in[10];
    const float* f1w      = (const float*)d_in[11];
    const float* f1b      = (const float*)d_in[12];
    const float* f2w      = (const float*)d_in[13];
    const float* f2b      = (const float*)d_in[14];
    float* out = (float*)d_out;

    float *qb, *kb, *vb, *ab, *tb, *xb, *fb, *gb, *Mb, *Zb, *nz, *wt;
    cudaGetSymbolAddress((void**)&qb, g_q);
    cudaGetSymbolAddress((void**)&kb, g_k);
    cudaGetSymbolAddress((void**)&vb, g_v);
    cudaGetSymbolAddress((void**)&ab, g_attn);
    cudaGetSymbolAddress((void**)&tb, g_tmp);
    cudaGetSymbolAddress((void**)&xb, g_x);
    cudaGetSymbolAddress((void**)&fb, g_ff);
    cudaGetSymbolAddress((void**)&gb, g_tgt);
    cudaGetSymbolAddress((void**)&Mb, g_M);
    cudaGetSymbolAddress((void**)&Zb, g_Z);
    cudaGetSymbolAddress((void**)&nz, g_noise);
    cudaGetSymbolAddress((void**)&wt, g_wtf);

    float* wqkv = wt;
    float* wout = wqkv + 6291456;
    float* wf1  = wout + 2097152;
    float* wf2  = wf1  + 8388608;

    cudaFuncSetAttribute(tgemm_kernel<false, true, false, false>, cudaFuncAttributeMaxDynamicSharedMemorySize, TGEMM_SMEM);
    cudaFuncSetAttribute(tgemm_kernel<true, false, true, true>,   cudaFuncAttributeMaxDynamicSharedMemorySize, TGEMM_SMEM);
    cudaFuncSetAttribute(qkv_kernel, cudaFuncAttributeMaxDynamicSharedMemorySize, TGEMM_SMEM);
    cudaFuncSetAttribute(attn_kernel, cudaFuncAttributeMaxDynamicSharedMemorySize, ATTN_SMEM);
    cudaFuncSetAttribute(attnmap_kernel, cudaFuncAttributeMaxDynamicSharedMemorySize, ATTNMAP_SMEM);

    noise_kernel<<<16, 256>>>(nz);
    wcvt_kernel<<<6291456 / 1024, 256>>>(ipw, wqkv, 6291456 / 4);
    wcvt_kernel<<<2097152 / 1024, 256>>>(ow,  wout, 2097152 / 4);
    wcvt_kernel<<<8388608 / 1024, 256>>>(f1w, wf1,  8388608 / 4);
    wcvt_kernel<<<8388608 / 1024, 256>>>(f2w, wf2,  8388608 / 4);

    for (int i = 0; i < 2; i++) {
        const float* xin = i ? gb : query;
        const float* W   = wqkv + (size_t)i * 3 * D_ * D_;
        const float* Bi  = ipb + (size_t)i * 3 * D_;

        qkv_kernel<<<dim3(8, 96), 256, TGEMM_SMEM>>>(xin, key_in, value_in, W, Bi, qb, kb, vb);

        attn_kernel<<<dim3(L_ / QROWS, H_, N_), 512, ATTN_SMEM>>>(qb, kb, vb, nz + i * 2048, ab, Mb, Zb);

        tgemm_kernel<false, true, false, false><<<dim3(8, 64), 256, TGEMM_SMEM>>>(
            ab, wout + (size_t)i * D_ * D_, ob + i * D_, tb, xin, ML, D_, D_, 1.f);
        ln_kernel<<<ML, 256>>>(tb, ln1g + i * D_, ln1b + i * D_, xb);

        tgemm_kernel<true, false, true, true><<<dim3(32, 64), 256, TGEMM_SMEM>>>(
            xb, wf1 + (size_t)i * FF_ * D_, f1b + i * FF_, fb, nullptr, ML, FF_, D_, 1.f);
        tgemm_kernel<false, true, false, false><<<dim3(8, 64), 256, TGEMM_SMEM>>>(
            fb, wf2 + (size_t)i * D_ * FF_, f2b + i * D_, tb, xb, ML, D_, FF_, 1.f);
        ln_kernel<<<ML, 256>>>(tb, ln2g + i * D_, ln2b + i * D_, i ? out : gb);
    }

    attnmap_kernel<<<dim3(L_ / 128, S_ / 64, N_), 256, ATTNMAP_SMEM>>>(qb, kb, Mb, Zb, out + (size_t)ML * D_);
}

// round 13
// speedup vs baseline: 1.0491x; 1.0491x over previous
#include <cuda_runtime.h>
#include <cstdint>
#include <math.h>

#define D_   1024
#define H_   16
#define HD_  64
#define FF_  4096
#define S_   1024
#define N_   2
#define L_   4096
#define ML   (L_*N_)
#define MS   (S_*N_)

// ---------------- scratch ----------------
__device__ float g_q[(size_t)ML*D_];
__device__ float g_k[(size_t)MS*D_];
__device__ float g_v[(size_t)MS*D_];
__device__ float g_attn[(size_t)ML*D_];
__device__ float g_tmp[(size_t)ML*D_];
__device__ float g_x[(size_t)ML*D_];
__device__ float g_ff[(size_t)ML*FF_];
__device__ float g_tgt[(size_t)ML*D_];
__device__ float g_M[(size_t)N_*H_*L_];
__device__ float g_Z[(size_t)N_*H_*L_];
__device__ float g_noise[2*N_*H_*HD_];
__device__ float g_wtf[25165824];   // tf32-rounded weights: qkv|out|ff1|ff2

// ---------------- threefry2x32 ----------------
__device__ __forceinline__ uint32_t rotl32(uint32_t x, int r) {
    return (x << r) | (x >> (32 - r));
}
__device__ __forceinline__ void threefry2x32(uint32_t k0, uint32_t k1,
                                             uint32_t x0, uint32_t x1,
                                             uint32_t& o0, uint32_t& o1) {
    uint32_t ks[3] = {k0, k1, k0 ^ k1 ^ 0x1BD11BDAu};
    const int rot[2][4] = {{13, 15, 26, 6}, {17, 29, 16, 24}};
    x0 += ks[0]; x1 += ks[1];
#pragma unroll
    for (int g = 0; g < 5; g++) {
        const int* r = rot[g & 1];
#pragma unroll
        for (int j = 0; j < 4; j++) {
            x0 += x1; x1 = rotl32(x1, r[j]); x1 ^= x0;
        }
        x0 += ks[(g + 1) % 3];
        x1 += ks[(g + 2) % 3] + (uint32_t)(g + 1);
    }
    o0 = x0; o1 = x1;
}

__global__ void noise_kernel(float* __restrict__ noise) {
    int t = blockIdx.x * blockDim.x + threadIdx.x;
    if (t >= 2 * 2048) return;
    int layer = t >> 11;
    int idx = t & 2047;
    uint32_t ka, kb;
    threefry2x32(0u, 42u, 0u, (uint32_t)layer, ka, kb);
    uint32_t o0, o1;
    threefry2x32(ka, kb, 0u, (uint32_t)idx, o0, o1);
    uint32_t bits = o0 ^ o1;
    uint32_t fb = (bits >> 9) | 0x3f800000u;
    float f = __uint_as_float(fb) - 1.0f;
    const float lo = -0.99999994f;
    float u = fmaf(f, 2.0f, lo);
    u = fmaxf(u, lo);
    noise[t] = 1.41421356237309515f * erfinvf(u);
}

// ---------------- tf32 / mma helpers ----------------
__device__ __forceinline__ uint32_t tf32bits(float x) {
    float y;
    asm("cvt.rna.tf32.f32 %0, %1;" : "=f"(y) : "f"(x));
    return __float_as_uint(y);
}
__device__ __forceinline__ float tf32round(float x) {
    float y;
    asm("cvt.rna.tf32.f32 %0, %1;" : "=f"(y) : "f"(x));
    return y;
}
__device__ __forceinline__ void mma_tf32(float* c, const uint32_t* a, const uint32_t* b) {
    asm volatile(
        "mma.sync.aligned.m16n8k8.row.col.f32.tf32.tf32.f32 "
        "{%0,%1,%2,%3}, {%4,%5,%6,%7}, {%8,%9}, {%0,%1,%2,%3};"
        : "+f"(c[0]), "+f"(c[1]), "+f"(c[2]), "+f"(c[3])
        : "r"(a[0]), "r"(a[1]), "r"(a[2]), "r"(a[3]), "r"(b[0]), "r"(b[1]));
}
__device__ __forceinline__ void cp16(uint32_t dst, const void* src) {
    asm volatile("cp.async.cg.shared.global [%0], [%1], 16;" :: "r"(dst), "l"(src));
}

// weight tf32 pre-rounding
__global__ void wcvt_kernel(const float* __restrict__ src, float* __restrict__ dst, int n4) {
    int i = blockIdx.x * blockDim.x + threadIdx.x;
    if (i >= n4) return;
    float4 v = *(const float4*)(src + (size_t)i * 4);
    v.x = tf32round(v.x); v.y = tf32round(v.y);
    v.z = tf32round(v.z); v.w = tf32round(v.w);
    *(float4*)(dst + (size_t)i * 4) = v;
}

// ---------------- TF32 GEMM core, cp.async 2-stage, BK=32 (R8 proven config) ----------------
#define GPAD 36
#define GSTG (128*GPAD)
#define TGEMM_SMEM (4*GSTG*4)

template<bool RELU, bool RES, bool ACVT, bool OCVT>
__device__ __forceinline__ void tgemm_core(
    const float* __restrict__ Ap, const float* __restrict__ Bp,
    const float* __restrict__ bias, float* __restrict__ C,
    const float* __restrict__ Res,
    int crow0, int ccol0, int Nn, int K, float postscale, float* smf) {
    const uint32_t smem_u32 = (uint32_t)__cvta_generic_to_shared(smf);
    const int tid = threadIdx.x;
    const int warp = tid >> 5, lane = tid & 31;
    const int g = lane >> 2, tig = lane & 3;
    const int wm = (warp >> 1) * 32;
    const int wn = (warp & 1) * 64;

    float acc[2][8][4];
#pragma unroll
    for (int mt = 0; mt < 2; mt++)
#pragma unroll
        for (int nt = 0; nt < 8; nt++)
#pragma unroll
            for (int j = 0; j < 4; j++) acc[mt][nt][j] = 0.f;

    auto load_stage = [&](int buf, int k0) {
#pragma unroll
        for (int u = 0; u < 4; u++) {
            int idx = tid + u * 256;
            int r = idx >> 3;
            int c = (idx & 7) << 2;
            cp16(smem_u32 + (uint32_t)((buf * GSTG + r * GPAD + c) << 2),
                 Ap + (size_t)r * K + k0 + c);
            cp16(smem_u32 + (uint32_t)(((2 + buf) * GSTG + r * GPAD + c) << 2),
                 Bp + (size_t)r * K + k0 + c);
        }
        asm volatile("cp.async.commit_group;");
    };

    auto acv = [](float x) -> uint32_t {
        return ACVT ? tf32bits(x) : __float_as_uint(x);
    };

    load_stage(0, 0);
    int buf = 0;
    for (int k0 = 0; k0 < K; k0 += 32) {
        if (k0 + 32 < K) {
            load_stage(buf ^ 1, k0 + 32);
            asm volatile("cp.async.wait_group 1;");
        } else {
            asm volatile("cp.async.wait_group 0;");
        }
        __syncthreads();
        const float* As = smf + buf * GSTG;
        const float* Bs = smf + (2 + buf) * GSTG;

        uint32_t af[2][2][4], bf[2][8][2];
        auto frag_load = [&](int slot, int ks) {
            int kk = ks * 8 + tig;
#pragma unroll
            for (int mt = 0; mt < 2; mt++) {
                int col = wm + mt * 16 + g;
                af[slot][mt][0] = acv(As[col * GPAD + kk]);
                af[slot][mt][1] = acv(As[(col + 8) * GPAD + kk]);
                af[slot][mt][2] = acv(As[col * GPAD + kk + 4]);
                af[slot][mt][3] = acv(As[(col + 8) * GPAD + kk + 4]);
            }
#pragma unroll
            for (int nt = 0; nt < 8; nt++) {
                int coln = wn + nt * 8 + g;
                bf[slot][nt][0] = __float_as_uint(Bs[coln * GPAD + kk]);
                bf[slot][nt][1] = __float_as_uint(Bs[coln * GPAD + kk + 4]);
            }
        };

        frag_load(0, 0);
#pragma unroll
        for (int ks = 0; ks < 4; ks++) {
            const int cur = ks & 1;
            if (ks < 3) frag_load(cur ^ 1, ks + 1);
#pragma unroll
            for (int nt = 0; nt < 8; nt++) {
                mma_tf32(acc[0][nt], af[cur][0], bf[cur][nt]);
                mma_tf32(acc[1][nt], af[cur][1], bf[cur][nt]);
            }
        }
        __syncthreads();
        buf ^= 1;
    }

#pragma unroll
    for (int mt = 0; mt < 2; mt++) {
        int r0 = crow0 + wm + mt * 16 + g;
        int r1 = r0 + 8;
#pragma unroll
        for (int nt = 0; nt < 8; nt++) {
            int cb = ccol0 + wn + nt * 8 + 2 * tig;
            float b0 = bias[cb], b1 = bias[cb + 1];
            float v00 = (acc[mt][nt][0] + b0) * postscale;
            float v01 = (acc[mt][nt][1] + b1) * postscale;
            float v10 = (acc[mt][nt][2] + b0) * postscale;
            float v11 = (acc[mt][nt][3] + b1) * postscale;
            if (RELU) {
                v00 = fmaxf(v00, 0.f); v01 = fmaxf(v01, 0.f);
                v10 = fmaxf(v10, 0.f); v11 = fmaxf(v11, 0.f);
            }
            size_t o0 = (size_t)r0 * Nn + cb;
            size_t o1 = (size_t)r1 * Nn + cb;
            if (RES) {
                float2 rA = *(const float2*)(Res + o0);
                float2 rB = *(const float2*)(Res + o1);
                v00 += rA.x; v01 += rA.y; v10 += rB.x; v11 += rB.y;
            }
            if (OCVT) {
                v00 = tf32round(v00); v01 = tf32round(v01);
                v10 = tf32round(v10); v11 = tf32round(v11);
            }
            *(float2*)(C + o0) = make_float2(v00, v01);
            *(float2*)(C + o1) = make_float2(v10, v11);
        }
    }
}

template<bool RELU, bool RES, bool ACVT, bool OCVT>
__global__ void __launch_bounds__(256) tgemm_kernel(
    const float* __restrict__ A, const float* __restrict__ B,
    const float* __restrict__ bias, float* __restrict__ C,
    const float* __restrict__ Res, int M, int Nn, int K, float postscale) {
    extern __shared__ float smf[];
    tgemm_core<RELU, RES, ACVT, OCVT>(A + (size_t)blockIdx.y * 128 * K,
                                      B + (size_t)blockIdx.x * 128 * K,
                                      bias, C, Res,
                                      blockIdx.y * 128, blockIdx.x * 128, Nn, K, postscale, smf);
}

// fused q/k/v projection: grid (8, 96); outputs tf32-rounded
__global__ void __launch_bounds__(256) qkv_kernel(
    const float* __restrict__ xin, const float* __restrict__ keyin,
    const float* __restrict__ valin, const float* __restrict__ W,
    const float* __restrict__ Bi,
    float* __restrict__ qb, float* __restrict__ kb, float* __restrict__ vb) {
    extern __shared__ float smf[];
    const int bm = blockIdx.y, bn = blockIdx.x;
    if (bm < 64) {
        tgemm_core<false, false, true, true>(xin + (size_t)bm * 128 * D_,
                                 W + (size_t)bn * 128 * D_, Bi, qb, nullptr,
                                 bm * 128, bn * 128, D_, D_, 0.125f, smf);
    } else if (bm < 80) {
        tgemm_core<false, false, true, true>(keyin + (size_t)(bm - 64) * 128 * D_,
                                 W + (size_t)(D_ + bn * 128) * D_, Bi + D_, kb, nullptr,
                                 (bm - 64) * 128, bn * 128, D_, D_, 1.f, smf);
    } else {
        tgemm_core<false, false, true, true>(valin + (size_t)(bm - 80) * 128 * D_,
                                 W + (size_t)(2 * D_ + bn * 128) * D_, Bi + 2 * D_, vb, nullptr,
                                 (bm - 80) * 128, bn * 128, D_, D_, 1.f, smf);
    }
}

// ---------------- tensor-core flash attention: 512 thr, 256-row Q tile ----------------
#define PPAD 68
#define KPK  68
#define KPV  72
#define QROWS 256
#define ATTN_SMEM ((QROWS*PPAD + 2*64*KPK + 2*64*KPV)*4)
__global__ void __launch_bounds__(512) attn_kernel(
    const float* __restrict__ Q, const float* __restrict__ Kb, const float* __restrict__ Vb,
    const float* __restrict__ noise, float* __restrict__ Out,
    float* __restrict__ Mb, float* __restrict__ Zb) {
    extern __shared__ uint32_t su[];
    uint32_t* p_s = su;
    const uint32_t smem_u32 = (uint32_t)__cvta_generic_to_shared(su);
    const int n = blockIdx.z, h = blockIdx.y, l0 = blockIdx.x * QROWS;
    const int tid = threadIdx.x;
    const int warp = tid >> 5, lane = tid & 31;
    const int g = lane >> 2, tig = lane & 3;
    const int wm = warp * 16;

    auto kv_prefetch = [&](int buf, int s0) {
        uint32_t kbase = smem_u32 + (uint32_t)((QROWS * PPAD + buf * 64 * KPK) << 2);
        uint32_t vbase = smem_u32 + (uint32_t)((QROWS * PPAD + 2 * 64 * KPK + buf * 64 * KPV) << 2);
#pragma unroll
        for (int u = 0; u < 2; u++) {
            int t = tid + u * 512;
            int s = t >> 4, dc = (t & 15) << 2;
            size_t goff = ((size_t)(s0 + s) * N_ + n) * D_ + h * HD_ + dc;
            cp16(kbase + (uint32_t)((s * KPK + dc) << 2), Kb + goff);
            cp16(vbase + (uint32_t)((s * KPV + dc) << 2), Vb + goff);
        }
        asm volatile("cp.async.commit_group;");
    };

    kv_prefetch(0, 0);

    for (int t = tid; t < QROWS * 16; t += 512) {
        int r = t >> 4, dc = (t & 15) << 2;
        *(uint4*)(p_s + r * PPAD + dc) =
            *(const uint4*)(Q + ((size_t)(l0 + r) * N_ + n) * D_ + h * HD_ + dc);
    }
    __syncthreads();
    uint32_t qf[8][4];
#pragma unroll
    for (int ks = 0; ks < 8; ks++) {
        int kk = ks * 8 + tig;
        qf[ks][0] = p_s[(wm + g) * PPAD + kk];
        qf[ks][1] = p_s[(wm + g + 8) * PPAD + kk];
        qf[ks][2] = p_s[(wm + g) * PPAD + kk + 4];
        qf[ks][3] = p_s[(wm + g + 8) * PPAD + kk + 4];
    }

    float m0 = -1e30f, m1 = -1e30f, l0s = 0.f, l1s = 0.f;
    float acc_o[8][4];
#pragma unroll
    for (int nt = 0; nt < 8; nt++)
#pragma unroll
        for (int j = 0; j < 4; j++) acc_o[nt][j] = 0.f;

    for (int c = 0; c < 16; c++) {
        asm volatile("cp.async.wait_group 0;");
        __syncthreads();
        if (c + 1 < 16) kv_prefetch((c + 1) & 1, (c + 1) * 64);
        const uint32_t* k_s = su + QROWS * PPAD + (c & 1) * 64 * KPK;
        const uint32_t* v_s = su + QROWS * PPAD + 2 * 64 * KPK + (c & 1) * 64 * KPV;

        float acc_s[8][4];
#pragma unroll
        for (int nt = 0; nt < 8; nt++)
#pragma unroll
            for (int j = 0; j < 4; j++) acc_s[nt][j] = 0.f;
#pragma unroll
        for (int ks = 0; ks < 8; ks++) {
            int kk = ks * 8 + tig;
#pragma unroll
            for (int nt = 0; nt < 8; nt++) {
                uint32_t kf[2];
                kf[0] = k_s[(nt * 8 + g) * KPK + kk];
                kf[1] = k_s[(nt * 8 + g) * KPK + kk + 4];
                mma_tf32(acc_s[nt], qf[ks], kf);
            }
        }

        float cm0 = -1e30f, cm1 = -1e30f;
#pragma unroll
        for (int nt = 0; nt < 8; nt++) {
            cm0 = fmaxf(cm0, fmaxf(acc_s[nt][0], acc_s[nt][1]));
            cm1 = fmaxf(cm1, fmaxf(acc_s[nt][2], acc_s[nt][3]));
        }
        cm0 = fmaxf(cm0, __shfl_xor_sync(0xffffffffu, cm0, 1));
        cm0 = fmaxf(cm0, __shfl_xor_sync(0xffffffffu, cm0, 2));
        cm1 = fmaxf(cm1, __shfl_xor_sync(0xffffffffu, cm1, 1));
        cm1 = fmaxf(cm1, __shfl_xor_sync(0xffffffffu, cm1, 2));
        float mn0 = fmaxf(m0, cm0), mn1 = fmaxf(m1, cm1);
        float corr0 = __expf(m0 - mn0), corr1 = __expf(m1 - mn1);
        float rs0 = 0.f, rs1 = 0.f;
#pragma unroll
        for (int nt = 0; nt < 8; nt++) {
            float p00 = __expf(acc_s[nt][0] - mn0);
            float p01 = __expf(acc_s[nt][1] - mn0);
            float p10 = __expf(acc_s[nt][2] - mn1);
            float p11 = __expf(acc_s[nt][3] - mn1);
            rs0 += p00 + p01; rs1 += p10 + p11;
            uint2 a = make_uint2(tf32bits(p00), tf32bits(p01));
            uint2 b = make_uint2(tf32bits(p10), tf32bits(p11));
            *(uint2*)(p_s + (wm + g) * PPAD + nt * 8 + 2 * tig) = a;
            *(uint2*)(p_s + (wm + g + 8) * PPAD + nt * 8 + 2 * tig) = b;
        }
        rs0 += __shfl_xor_sync(0xffffffffu, rs0, 1);
        rs0 += __shfl_xor_sync(0xffffffffu, rs0, 2);
        rs1 += __shfl_xor_sync(0xffffffffu, rs1, 1);
        rs1 += __shfl_xor_sync(0xffffffffu, rs1, 2);
        l0s = l0s * corr0 + rs0;
        l1s = l1s * corr1 + rs1;
        m0 = mn0; m1 = mn1;
#pragma unroll
        for (int nt = 0; nt < 8; nt++) {
            acc_o[nt][0] *= corr0; acc_o[nt][1] *= corr0;
            acc_o[nt][2] *= corr1; acc_o[nt][3] *= corr1;
        }
        __syncwarp();

#pragma unroll
        for (int ks = 0; ks < 8; ks++) {
            int kk = ks * 8 + tig;
            uint32_t pf[4];
            pf[0] = p_s[(wm + g) * PPAD + kk];
            pf[1] = p_s[(wm + g + 8) * PPAD + kk];
            pf[2] = p_s[(wm + g) * PPAD + kk + 4];
            pf[3] = p_s[(wm + g + 8) * PPAD + kk + 4];
#pragma unroll
            for (int nt = 0; nt < 8; nt++) {
                uint32_t vf[2];
                vf[0] = v_s[kk * KPV + nt * 8 + g];
                vf[1] = v_s[(kk + 4) * KPV + nt * 8 + g];
                mma_tf32(acc_o[nt], pf, vf);
            }
        }
        __syncwarp();
    }

    {
        float mf0 = fmaxf(m0, 0.f), mf1 = fmaxf(m1, 0.f);
        float c0 = __expf(m0 - mf0), c1 = __expf(m1 - mf1);
        float pw0 = __expf(-mf0), pw1 = __expf(-mf1);
        float lf0 = l0s * c0 + pw0, lf1 = l1s * c1 + pw1;
        float inv0 = 1.f / lf0, inv1 = 1.f / lf1;
        int r0 = l0 + wm + g, r1 = r0 + 8;
        const float* nb = noise + (n * H_ + h) * HD_;
        float* o0p = Out + ((size_t)r0 * N_ + n) * D_ + h * HD_;
        float* o1p = Out + ((size_t)r1 * N_ + n) * D_ + h * HD_;
#pragma unroll
        for (int nt = 0; nt < 8; nt++) {
            int col = nt * 8 + 2 * tig;
            float nv0 = nb[col], nv1 = nb[col + 1];
            *(float2*)(o0p + col) = make_float2(
                tf32round((acc_o[nt][0] * c0 + pw0 * nv0) * inv0),
                tf32round((acc_o[nt][1] * c0 + pw0 * nv1) * inv0));
            *(float2*)(o1p + col) = make_float2(
                tf32round((acc_o[nt][2] * c1 + pw1 * nv0) * inv1),
                tf32round((acc_o[nt][3] * c1 + pw1 * nv1) * inv1));
        }
        if (tig == 0) {
            size_t base = (size_t)(n * H_ + h) * L_;
            Mb[base + r0] = mf0; Zb[base + r0] = lf0;
            Mb[base + r1] = mf1; Zb[base + r1] = lf1;
        }
    }
}

// ---------------- tensor-core attn_map (pad 68) ----------------
#define AMQ 68
#define AMK 68
#define ATTNMAP_SMEM ((128*AMQ + 64*AMK)*4)
__global__ void __launch_bounds__(256) attnmap_kernel(
    const float* __restrict__ Q, const float* __restrict__ Kb,
    const float* __restrict__ Mb, const float* __restrict__ Zb,
    float* __restrict__ Out2) {
    extern __shared__ uint32_t su[];
    uint32_t* q_s = su;
    uint32_t* k_s = su + 128 * AMQ;
    const int n = blockIdx.z, l0 = blockIdx.x * 128, s0 = blockIdx.y * 64;
    const int tid = threadIdx.x;
    const int warp = tid >> 5, lane = tid & 31;
    const int g = lane >> 2, tig = lane & 3;
    const int wm = warp * 16;

    float acc[8][4];
#pragma unroll
    for (int nt = 0; nt < 8; nt++)
#pragma unroll
        for (int j = 0; j < 4; j++) acc[nt][j] = 0.f;

    for (int h = 0; h < H_; h++) {
        __syncthreads();
        for (int t = tid; t < 128 * 16; t += 256) {
            int r = t >> 4, dc = (t & 15) << 2;
            *(uint4*)(q_s + r * AMQ + dc) =
                *(const uint4*)(Q + ((size_t)(l0 + r) * N_ + n) * D_ + h * HD_ + dc);
        }
        for (int t = tid; t < 64 * 16; t += 256) {
            int s = t >> 4, dc = (t & 15) << 2;
            *(uint4*)(k_s + s * AMK + dc) =
                *(const uint4*)(Kb + ((size_t)(s0 + s) * N_ + n) * D_ + h * HD_ + dc);
        }
        __syncthreads();

        uint32_t qf[8][4];
#pragma unroll
        for (int ks = 0; ks < 8; ks++) {
            int kk = ks * 8 + tig;
            qf[ks][0] = q_s[(wm + g) * AMQ + kk];
            qf[ks][1] = q_s[(wm + g + 8) * AMQ + kk];
            qf[ks][2] = q_s[(wm + g) * AMQ + kk + 4];
            qf[ks][3] = q_s[(wm + g + 8) * AMQ + kk + 4];
        }
        float s_[8][4];
#pragma unroll
        for (int nt = 0; nt < 8; nt++)
#pragma unroll
            for (int j = 0; j < 4; j++) s_[nt][j] = 0.f;
#pragma unroll
        for (int ks = 0; ks < 8; ks++) {
            int kk = ks * 8 + tig;
#pragma unroll
            for (int nt = 0; nt < 8; nt++) {
                uint32_t kf[2];
                kf[0] = k_s[(nt * 8 + g) * AMK + kk];
                kf[1] = k_s[(nt * 8 + g) * AMK + kk + 4];
                mma_tf32(s_[nt], qf[ks], kf);
            }
        }

        size_t mz = (size_t)(n * H_ + h) * L_;
        int r0 = l0 + wm + g, r1 = r0 + 8;
        float mf0 = Mb[mz + r0], iz0 = 1.f / Zb[mz + r0];
        float mf1 = Mb[mz + r1], iz1 = 1.f / Zb[mz + r1];
#pragma unroll
        for (int nt = 0; nt < 8; nt++) {
            float w00 = __expf(s_[nt][0] - mf0) * iz0;
            float w01 = __expf(s_[nt][1] - mf0) * iz0;
            float w10 = __expf(s_[nt][2] - mf1) * iz1;
            float w11 = __expf(s_[nt][3] - mf1) * iz1;
            acc[nt][0] += __fdividef(1.f, 1.f + __expf(-w00));
            acc[nt][1] += __fdividef(1.f, 1.f + __expf(-w01));
            acc[nt][2] += __fdividef(1.f, 1.f + __expf(-w10));
            acc[nt][3] += __fdividef(1.f, 1.f + __expf(-w11));
        }
    }

    int r0 = l0 + wm + g, r1 = r0 + 8;
#pragma unroll
    for (int nt = 0; nt < 8; nt++) {
        int col = s0 + nt * 8 + 2 * tig;
        *(float2*)(Out2 + ((size_t)n * L_ + r0) * S_ + col) =
            make_float2(acc[nt][0] * (1.f / 16.f), acc[nt][1] * (1.f / 16.f));
        *(float2*)(Out2 + ((size_t)n * L_ + r1) * S_ + col) =
            make_float2(acc[nt][2] * (1.f / 16.f), acc[nt][3] * (1.f / 16.f));
    }
}

// ---------------- layernorm ----------------
__global__ void __launch_bounds__(256) ln_kernel(
    const float* __restrict__ X, const float* __restrict__ g,
    const float* __restrict__ b, float* __restrict__ Y) {
    const int row = blockIdx.x;
    const int tid = threadIdx.x;
    const float* x = X + (size_t)row * D_;
    float4 v = *(const float4*)(x + tid * 4);
    __shared__ float red[8];
    const int wid = tid >> 5, lane = tid & 31;

    float s = v.x + v.y + v.z + v.w;
#pragma unroll
    for (int o = 16; o; o >>= 1) s += __shfl_xor_sync(0xffffffffu, s, o);
    if (!lane) red[wid] = s;
    __syncthreads();
    float tot = 0.f;
#pragma unroll
    for (int w = 0; w < 8; w++) tot += red[w];
    float mean = tot * (1.f / D_);

    float dx = v.x - mean, dy = v.y - mean, dz = v.z - mean, dw = v.w - mean;
    float ss = dx * dx + dy * dy + dz * dz + dw * dw;
#pragma unroll
    for (int o = 16; o; o >>= 1) ss += __shfl_xor_sync(0xffffffffu, ss, o);
    __syncthreads();
    if (!lane) red[wid] = ss;
    __syncthreads();
    float tss = 0.f;
#pragma unroll
    for (int w = 0; w < 8; w++) tss += red[w];
    float inv = rsqrtf(tss * (1.f / D_) + 1e-5f);

    const int c = tid * 4;
    float4 gv = *(const float4*)(g + c);
    float4 bv = *(const float4*)(b + c);
    float4 o;
    o.x = dx * inv * gv.x + bv.x;
    o.y = dy * inv * gv.y + bv.y;
    o.z = dz * inv * gv.z + bv.z;
    o.w = dw * inv * gv.w + bv.w;
    *(float4*)(Y + (size_t)row * D_ + c) = o;
}

// ---------------- orchestration ----------------
extern "C" void kernel_launch(void* const* d_in, const int* in_sizes, int n_in,
                              void* d_out, int out_size) {
    const float* key_in   = (const float*)d_in[0];
    const float* value_in = (const float*)d_in[1];
    const float* query    = (const float*)d_in[2];
    const float* ipw      = (const float*)d_in[3];
    const float* ipb      = (const float*)d_in[4];
    const float* ow       = (const float*)d_in[5];
    const float* ob       = (const float*)d_in[6];
    const float* ln1g     = (const float*)d_in[7];
    const float* ln1b     = (const float*)d_in[8];
    const float* ln2g     = (const float*)d_in[9];
    const float* ln2b     = (const float*)d_in[10];
    const float* f1w      = (const float*)d_in[11];
    const float* f1b      = (const float*)d_in[12];
    const float* f2w      = (const float*)d_in[13];
    const float* f2b      = (const float*)d_in[14];
    float* out = (float*)d_out;

    float *qb, *kb, *vb, *ab, *tb, *xb, *fb, *gb, *Mb, *Zb, *nz, *wt;
    cudaGetSymbolAddress((void**)&qb, g_q);
    cudaGetSymbolAddress((void**)&kb, g_k);
    cudaGetSymbolAddress((void**)&vb, g_v);
    cudaGetSymbolAddress((void**)&ab, g_attn);
    cudaGetSymbolAddress((void**)&tb, g_tmp);
    cudaGetSymbolAddress((void**)&xb, g_x);
    cudaGetSymbolAddress((void**)&fb, g_ff);
    cudaGetSymbolAddress((void**)&gb, g_tgt);
    cudaGetSymbolAddress((void**)&Mb, g_M);
    cudaGetSymbolAddress((void**)&Zb, g_Z);
    cudaGetSymbolAddress((void**)&nz, g_noise);
    cudaGetSymbolAddress((void**)&wt, g_wtf);

    float* wqkv = wt;
    float* wout = wqkv + 6291456;
    float* wf1  = wout + 2097152;
    float* wf2  = wf1  + 8388608;

    cudaFuncSetAttribute(tgemm_kernel<false, true, false, false>, cudaFuncAttributeMaxDynamicSharedMemorySize, TGEMM_SMEM);
    cudaFuncSetAttribute(tgemm_kernel<true, false, true, true>,   cudaFuncAttributeMaxDynamicSharedMemorySize, TGEMM_SMEM);
    cudaFuncSetAttribute(qkv_kernel, cudaFuncAttributeMaxDynamicSharedMemorySize, TGEMM_SMEM);
    cudaFuncSetAttribute(attn_kernel, cudaFuncAttributeMaxDynamicSharedMemorySize, ATTN_SMEM);
    cudaFuncSetAttribute(attnmap_kernel, cudaFuncAttributeMaxDynamicSharedMemorySize, ATTNMAP_SMEM);

    noise_kernel<<<16, 256>>>(nz);
    wcvt_kernel<<<6291456 / 1024, 256>>>(ipw, wqkv, 6291456 / 4);
    wcvt_kernel<<<2097152 / 1024, 256>>>(ow,  wout, 2097152 / 4);
    wcvt_kernel<<<8388608 / 1024, 256>>>(f1w, wf1,  8388608 / 4);
    wcvt_kernel<<<8388608 / 1024, 256>>>(f2w, wf2,  8388608 / 4);

    for (int i = 0; i < 2; i++) {
        const float* xin = i ? gb : query;
        const float* W   = wqkv + (size_t)i * 3 * D_ * D_;
        const float* Bi  = ipb + (size_t)i * 3 * D_;

        qkv_kernel<<<dim3(8, 96), 256, TGEMM_SMEM>>>(xin, key_in, value_in, W, Bi, qb, kb, vb);

        attn_kernel<<<dim3(L_ / QROWS, H_, N_), 512, ATTN_SMEM>>>(qb, kb, vb, nz + i * 2048, ab, Mb, Zb);

        tgemm_kernel<false, true, false, false><<<dim3(8, 64), 256, TGEMM_SMEM>>>(
            ab, wout + (size_t)i * D_ * D_, ob + i * D_, tb, xin, ML, D_, D_, 1.f);
        ln_kernel<<<ML, 256>>>(tb, ln1g + i * D_, ln1b + i * D_, xb);

        tgemm_kernel<true, false, true, true><<<dim3(32, 64), 256, TGEMM_SMEM>>>(
            xb, wf1 + (size_t)i * FF_ * D_, f1b + i * FF_, fb, nullptr, ML, FF_, D_, 1.f);
        tgemm_kernel<false, true, false, false><<<dim3(8, 64), 256, TGEMM_SMEM>>>(
            fb, wf2 + (size_t)i * D_ * FF_, f2b + i * D_, tb, xb, ML, D_, FF_, 1.f);
        ln_kernel<<<ML, 256>>>(tb, ln2g + i * D_, ln2b + i * D_, i ? out : gb);
    }

    attnmap_kernel<<<dim3(L_ / 128, S_ / 64, N_), 256, ATTNMAP_SMEM>>>(qb, kb, Mb, Zb, out + (size_t)ML * D_);
}

// round 15
// speedup vs baseline: 1.1406x; 1.0872x over previous
#include <cuda_runtime.h>
#include <cstdint>
#include <math.h>

#define D_   1024
#define H_   16
#define HD_  64
#define FF_  4096
#define S_   1024
#define N_   2
#define L_   4096
#define ML   (L_*N_)
#define MS   (S_*N_)

// ---------------- scratch ----------------
__device__ float g_q[(size_t)ML*D_];
__device__ float g_k[(size_t)MS*D_];
__device__ float g_v[(size_t)MS*D_];
__device__ float g_attn[(size_t)ML*D_];
__device__ float g_tmp[(size_t)ML*D_];
__device__ float g_x[(size_t)ML*D_];
__device__ float g_ff[(size_t)ML*FF_];
__device__ float g_tgt[(size_t)ML*D_];
__device__ float g_M[(size_t)N_*H_*L_];
__device__ float g_Z[(size_t)N_*H_*L_];
__device__ float g_noise[2*N_*H_*HD_];
__device__ float g_wtf[25165824];   // tf32-rounded weights: qkv|out|ff1|ff2

// ---------------- threefry2x32 ----------------
__device__ __forceinline__ uint32_t rotl32(uint32_t x, int r) {
    return (x << r) | (x >> (32 - r));
}
__device__ __forceinline__ void threefry2x32(uint32_t k0, uint32_t k1,
                                             uint32_t x0, uint32_t x1,
                                             uint32_t& o0, uint32_t& o1) {
    uint32_t ks[3] = {k0, k1, k0 ^ k1 ^ 0x1BD11BDAu};
    const int rot[2][4] = {{13, 15, 26, 6}, {17, 29, 16, 24}};
    x0 += ks[0]; x1 += ks[1];
#pragma unroll
    for (int g = 0; g < 5; g++) {
        const int* r = rot[g & 1];
#pragma unroll
        for (int j = 0; j < 4; j++) {
            x0 += x1; x1 = rotl32(x1, r[j]); x1 ^= x0;
        }
        x0 += ks[(g + 1) % 3];
        x1 += ks[(g + 2) % 3] + (uint32_t)(g + 1);
    }
    o0 = x0; o1 = x1;
}

__global__ void noise_kernel(float* __restrict__ noise) {
    int t = blockIdx.x * blockDim.x + threadIdx.x;
    if (t >= 2 * 2048) return;
    int layer = t >> 11;
    int idx = t & 2047;
    uint32_t ka, kb;
    threefry2x32(0u, 42u, 0u, (uint32_t)layer, ka, kb);
    uint32_t o0, o1;
    threefry2x32(ka, kb, 0u, (uint32_t)idx, o0, o1);
    uint32_t bits = o0 ^ o1;
    uint32_t fb = (bits >> 9) | 0x3f800000u;
    float f = __uint_as_float(fb) - 1.0f;
    const float lo = -0.99999994f;
    float u = fmaf(f, 2.0f, lo);
    u = fmaxf(u, lo);
    noise[t] = 1.41421356237309515f * erfinvf(u);
}

// ---------------- tf32 / mma / ldmatrix helpers ----------------
__device__ __forceinline__ uint32_t tf32bits(float x) {
    float y;
    asm("cvt.rna.tf32.f32 %0, %1;" : "=f"(y) : "f"(x));
    return __float_as_uint(y);
}
__device__ __forceinline__ float tf32round(float x) {
    float y;
    asm("cvt.rna.tf32.f32 %0, %1;" : "=f"(y) : "f"(x));
    return y;
}
__device__ __forceinline__ void mma_tf32(float* c, const uint32_t* a, const uint32_t* b) {
    asm volatile(
        "mma.sync.aligned.m16n8k8.row.col.f32.tf32.tf32.f32 "
        "{%0,%1,%2,%3}, {%4,%5,%6,%7}, {%8,%9}, {%0,%1,%2,%3};"
        : "+f"(c[0]), "+f"(c[1]), "+f"(c[2]), "+f"(c[3])
        : "r"(a[0]), "r"(a[1]), "r"(a[2]), "r"(a[3]), "r"(b[0]), "r"(b[1]));
}
__device__ __forceinline__ void cp16(uint32_t dst, const void* src) {
    asm volatile("cp.async.cg.shared.global [%0], [%1], 16;" :: "r"(dst), "l"(src));
}
__device__ __forceinline__ void ldsm4(uint32_t* r, uint32_t addr) {
    asm volatile("ldmatrix.sync.aligned.m8n8.x4.shared.b16 {%0,%1,%2,%3}, [%4];"
        : "=r"(r[0]), "=r"(r[1]), "=r"(r[2]), "=r"(r[3]) : "r"(addr));
}

// fused weight tf32 pre-rounding (qkv|out|ff1|ff2 regions)
__global__ void wcvt_all_kernel(const float* __restrict__ ipw, const float* __restrict__ ow,
                                const float* __restrict__ f1w, const float* __restrict__ f2w,
                                float* __restrict__ dst) {
    int i = blockIdx.x * blockDim.x + threadIdx.x;   // float4 index, total 6291456
    if (i >= 6291456) return;
    const float* src;
    int j = i;
    if (j < 1572864) src = ipw + (size_t)j * 4;
    else if (j < 2097152) src = ow + (size_t)(j - 1572864) * 4;
    else if (j < 4194304) src = f1w + (size_t)(j - 2097152) * 4;
    else src = f2w + (size_t)(j - 4194304) * 4;
    float4 v = *(const float4*)src;
    v.x = tf32round(v.x); v.y = tf32round(v.y);
    v.z = tf32round(v.z); v.w = tf32round(v.w);
    *(float4*)(dst + (size_t)i * 4) = v;
}

// ---------------- TF32 GEMM core, cp.async 2-stage, BK=32, ldmatrix frags ----------------
#define GPAD 36
#define GSTG (128*GPAD)
#define TGEMM_SMEM (4*GSTG*4)

template<bool RELU, bool RES, bool ACVT, bool OCVT>
__device__ __forceinline__ void tgemm_core(
    const float* __restrict__ Ap, const float* __restrict__ Bp,
    const float* __restrict__ bias, float* __restrict__ C,
    const float* __restrict__ Res,
    int crow0, int ccol0, int Nn, int K, float postscale, float* smf) {
    const uint32_t smem_u32 = (uint32_t)__cvta_generic_to_shared(smf);
    const int tid = threadIdx.x;
    const int warp = tid >> 5, lane = tid & 31;
    const int g = lane >> 2, tig = lane & 3;
    const int wm = (warp >> 1) * 32;
    const int wn = (warp & 1) * 64;

    // ldmatrix per-thread address pieces
    const int arow = ((lane >> 3) & 1) * 8 + (lane & 7);   // + mt*16 + wm
    const uint32_t akb = ((lane >> 4) & 1) * 16;           // k byte offset within 32B
    const int brow = ((lane >> 4) & 1) * 8 + (lane & 7);   // + p*16 + wn
    const uint32_t bkb = ((lane >> 3) & 1) * 16;

    float acc[2][8][4];
#pragma unroll
    for (int mt = 0; mt < 2; mt++)
#pragma unroll
        for (int nt = 0; nt < 8; nt++)
#pragma unroll
            for (int j = 0; j < 4; j++) acc[mt][nt][j] = 0.f;

    auto load_stage = [&](int buf, int k0) {
#pragma unroll
        for (int u = 0; u < 4; u++) {
            int idx = tid + u * 256;
            int r = idx >> 3;
            int c = (idx & 7) << 2;
            cp16(smem_u32 + (uint32_t)((buf * GSTG + r * GPAD + c) << 2),
                 Ap + (size_t)r * K + k0 + c);
            cp16(smem_u32 + (uint32_t)(((2 + buf) * GSTG + r * GPAD + c) << 2),
                 Bp + (size_t)r * K + k0 + c);
        }
        asm volatile("cp.async.commit_group;");
    };

    load_stage(0, 0);
    int buf = 0;
    for (int k0 = 0; k0 < K; k0 += 32) {
        if (k0 + 32 < K) {
            load_stage(buf ^ 1, k0 + 32);
            asm volatile("cp.async.wait_group 1;");
        } else {
            asm volatile("cp.async.wait_group 0;");
        }
        __syncthreads();

        const uint32_t aBase = smem_u32 + (uint32_t)(buf * GSTG * 4)
                             + (uint32_t)((wm + arow) * GPAD * 4) + akb;
        const uint32_t bBase = smem_u32 + (uint32_t)((2 + buf) * GSTG * 4)
                             + (uint32_t)((wn + brow) * GPAD * 4) + bkb;

        uint32_t af[2][2][4], bf[2][8][2];
        auto frag_load = [&](int slot, int ks) {
            uint32_t koff = (uint32_t)(ks * 32);
#pragma unroll
            for (int mt = 0; mt < 2; mt++) {
                ldsm4(af[slot][mt], aBase + (uint32_t)(mt * 16 * GPAD * 4) + koff);
                if (ACVT) {
#pragma unroll
                    for (int j = 0; j < 4; j++)
                        af[slot][mt][j] = tf32bits(__uint_as_float(af[slot][mt][j]));
                }
            }
#pragma unroll
            for (int p = 0; p < 4; p++) {
                uint32_t r[4];
                ldsm4(r, bBase + (uint32_t)(p * 16 * GPAD * 4) + koff);
                bf[slot][2 * p][0] = r[0];     bf[slot][2 * p][1] = r[1];
                bf[slot][2 * p + 1][0] = r[2]; bf[slot][2 * p + 1][1] = r[3];
            }
        };

        frag_load(0, 0);
#pragma unroll
        for (int ks = 0; ks < 4; ks++) {
            const int cur = ks & 1;
            if (ks < 3) frag_load(cur ^ 1, ks + 1);
#pragma unroll
            for (int nt = 0; nt < 8; nt++) {
                mma_tf32(acc[0][nt], af[cur][0], bf[cur][nt]);
                mma_tf32(acc[1][nt], af[cur][1], bf[cur][nt]);
            }
        }
        __syncthreads();
        buf ^= 1;
    }

#pragma unroll
    for (int mt = 0; mt < 2; mt++) {
        int r0 = crow0 + wm + mt * 16 + g;
        int r1 = r0 + 8;
#pragma unroll
        for (int nt = 0; nt < 8; nt++) {
            int cb = ccol0 + wn + nt * 8 + 2 * tig;
            float b0 = bias[cb], b1 = bias[cb + 1];
            float v00 = (acc[mt][nt][0] + b0) * postscale;
            float v01 = (acc[mt][nt][1] + b1) * postscale;
            float v10 = (acc[mt][nt][2] + b0) * postscale;
            float v11 = (acc[mt][nt][3] + b1) * postscale;
            if (RELU) {
                v00 = fmaxf(v00, 0.f); v01 = fmaxf(v01, 0.f);
                v10 = fmaxf(v10, 0.f); v11 = fmaxf(v11, 0.f);
            }
            size_t o0 = (size_t)r0 * Nn + cb;
            size_t o1 = (size_t)r1 * Nn + cb;
            if (RES) {
                float2 rA = *(const float2*)(Res + o0);
                float2 rB = *(const float2*)(Res + o1);
                v00 += rA.x; v01 += rA.y; v10 += rB.x; v11 += rB.y;
            }
            if (OCVT) {
                v00 = tf32round(v00); v01 = tf32round(v01);
                v10 = tf32round(v10); v11 = tf32round(v11);
            }
            *(float2*)(C + o0) = make_float2(v00, v01);
            *(float2*)(C + o1) = make_float2(v10, v11);
        }
    }
}

template<bool RELU, bool RES, bool ACVT, bool OCVT>
__global__ void __launch_bounds__(256) tgemm_kernel(
    const float* __restrict__ A, const float* __restrict__ B,
    const float* __restrict__ bias, float* __restrict__ C,
    const float* __restrict__ Res, int M, int Nn, int K, float postscale) {
    extern __shared__ float smf[];
    tgemm_core<RELU, RES, ACVT, OCVT>(A + (size_t)blockIdx.y * 128 * K,
                                      B + (size_t)blockIdx.x * 128 * K,
                                      bias, C, Res,
                                      blockIdx.y * 128, blockIdx.x * 128, Nn, K, postscale, smf);
}

// fused q/k/v projection: grid (8, 96); outputs tf32-rounded
__global__ void __launch_bounds__(256) qkv_kernel(
    const float* __restrict__ xin, const float* __restrict__ keyin,
    const float* __restrict__ valin, const float* __restrict__ W,
    const float* __restrict__ Bi,
    float* __restrict__ qb, float* __restrict__ kb, float* __restrict__ vb) {
    extern __shared__ float smf[];
    const int bm = blockIdx.y, bn = blockIdx.x;
    if (bm < 64) {
        tgemm_core<false, false, true, true>(xin + (size_t)bm * 128 * D_,
                                 W + (size_t)bn * 128 * D_, Bi, qb, nullptr,
                                 bm * 128, bn * 128, D_, D_, 0.125f, smf);
    } else if (bm < 80) {
        tgemm_core<false, false, true, true>(keyin + (size_t)(bm - 64) * 128 * D_,
                                 W + (size_t)(D_ + bn * 128) * D_, Bi + D_, kb, nullptr,
                                 (bm - 64) * 128, bn * 128, D_, D_, 1.f, smf);
    } else {
        tgemm_core<false, false, true, true>(valin + (size_t)(bm - 80) * 128 * D_,
                                 W + (size_t)(2 * D_ + bn * 128) * D_, Bi + 2 * D_, vb, nullptr,
                                 (bm - 80) * 128, bn * 128, D_, D_, 1.f, smf);
    }
}

// ---------------- tensor-core flash attention: 512 thr, 256-row Q tile, ldmatrix frags ----------------
#define PPAD 68
#define KPK  68
#define KPV  72
#define QROWS 256
#define ATTN_SMEM ((QROWS*PPAD + 2*64*KPK + 2*64*KPV)*4)
__global__ void __launch_bounds__(512) attn_kernel(
    const float* __restrict__ Q, const float* __restrict__ Kb, const float* __restrict__ Vb,
    const float* __restrict__ noise, float* __restrict__ Out,
    float* __restrict__ Mb, float* __restrict__ Zb) {
    extern __shared__ uint32_t su[];
    uint32_t* p_s = su;
    const uint32_t smem_u32 = (uint32_t)__cvta_generic_to_shared(su);
    const int n = blockIdx.z, h = blockIdx.y, l0 = blockIdx.x * QROWS;
    const int tid = threadIdx.x;
    const int warp = tid >> 5, lane = tid & 31;
    const int g = lane >> 2, tig = lane & 3;
    const int wm = warp * 16;

    // ldmatrix address pieces
    const int arow = ((lane >> 3) & 1) * 8 + (lane & 7);   // A-type (qf/pf)
    const uint32_t akb = ((lane >> 4) & 1) * 16;
    const int brow = ((lane >> 4) & 1) * 8 + (lane & 7);   // B-type (kf)
    const uint32_t bkb = ((lane >> 3) & 1) * 16;

    const uint32_t pAddr = smem_u32 + (uint32_t)((wm + arow) * PPAD * 4) + akb;

    auto kv_prefetch = [&](int buf, int s0) {
        uint32_t kbase = smem_u32 + (uint32_t)((QROWS * PPAD + buf * 64 * KPK) << 2);
        uint32_t vbase = smem_u32 + (uint32_t)((QROWS * PPAD + 2 * 64 * KPK + buf * 64 * KPV) << 2);
#pragma unroll
        for (int u = 0; u < 2; u++) {
            int t = tid + u * 512;
            int s = t >> 4, dc = (t & 15) << 2;
            size_t goff = ((size_t)(s0 + s) * N_ + n) * D_ + h * HD_ + dc;
            cp16(kbase + (uint32_t)((s * KPK + dc) << 2), Kb + goff);
            cp16(vbase + (uint32_t)((s * KPV + dc) << 2), Vb + goff);
        }
        asm volatile("cp.async.commit_group;");
    };

    kv_prefetch(0, 0);

    for (int t = tid; t < QROWS * 16; t += 512) {
        int r = t >> 4, dc = (t & 15) << 2;
        *(uint4*)(p_s + r * PPAD + dc) =
            *(const uint4*)(Q + ((size_t)(l0 + r) * N_ + n) * D_ + h * HD_ + dc);
    }
    __syncthreads();
    uint32_t qf[8][4];
#pragma unroll
    for (int ks = 0; ks < 8; ks++) ldsm4(qf[ks], pAddr + (uint32_t)(ks * 32));

    float m0 = -1e30f, m1 = -1e30f, l0s = 0.f, l1s = 0.f;
    float acc_o[8][4];
#pragma unroll
    for (int nt = 0; nt < 8; nt++)
#pragma unroll
        for (int j = 0; j < 4; j++) acc_o[nt][j] = 0.f;

    for (int c = 0; c < 16; c++) {
        asm volatile("cp.async.wait_group 0;");
        __syncthreads();
        if (c + 1 < 16) kv_prefetch((c + 1) & 1, (c + 1) * 64);
        const uint32_t kAddr = smem_u32 + (uint32_t)((QROWS * PPAD + (c & 1) * 64 * KPK) * 4)
                             + (uint32_t)(brow * KPK * 4) + bkb;
        const uint32_t* v_s = su + QROWS * PPAD + 2 * 64 * KPK + (c & 1) * 64 * KPV;

        float acc_s[8][4];
#pragma unroll
        for (int nt = 0; nt < 8; nt++)
#pragma unroll
            for (int j = 0; j < 4; j++) acc_s[nt][j] = 0.f;
#pragma unroll
        for (int ks = 0; ks < 8; ks++) {
            uint32_t koff = (uint32_t)(ks * 32);
#pragma unroll
            for (int p = 0; p < 4; p++) {
                uint32_t r[4];
                ldsm4(r, kAddr + (uint32_t)(p * 16 * KPK * 4) + koff);
                uint32_t kf0[2] = {r[0], r[1]};
                uint32_t kf1[2] = {r[2], r[3]};
                mma_tf32(acc_s[2 * p], qf[ks], kf0);
                mma_tf32(acc_s[2 * p + 1], qf[ks], kf1);
            }
        }

        float cm0 = -1e30f, cm1 = -1e30f;
#pragma unroll
        for (int nt = 0; nt < 8; nt++) {
            cm0 = fmaxf(cm0, fmaxf(acc_s[nt][0], acc_s[nt][1]));
            cm1 = fmaxf(cm1, fmaxf(acc_s[nt][2], acc_s[nt][3]));
        }
        cm0 = fmaxf(cm0, __shfl_xor_sync(0xffffffffu, cm0, 1));
        cm0 = fmaxf(cm0, __shfl_xor_sync(0xffffffffu, cm0, 2));
        cm1 = fmaxf(cm1, __shfl_xor_sync(0xffffffffu, cm1, 1));
        cm1 = fmaxf(cm1, __shfl_xor_sync(0xffffffffu, cm1, 2));
        float mn0 = fmaxf(m0, cm0), mn1 = fmaxf(m1, cm1);
        float corr0 = __expf(m0 - mn0), corr1 = __expf(m1 - mn1);
        float rs0 = 0.f, rs1 = 0.f;
#pragma unroll
        for (int nt = 0; nt < 8; nt++) {
            float p00 = __expf(acc_s[nt][0] - mn0);
            float p01 = __expf(acc_s[nt][1] - mn0);
            float p10 = __expf(acc_s[nt][2] - mn1);
            float p11 = __expf(acc_s[nt][3] - mn1);
            rs0 += p00 + p01; rs1 += p10 + p11;
            uint2 a = make_uint2(tf32bits(p00), tf32bits(p01));
            uint2 b = make_uint2(tf32bits(p10), tf32bits(p11));
            *(uint2*)(p_s + (wm + g) * PPAD + nt * 8 + 2 * tig) = a;
            *(uint2*)(p_s + (wm + g + 8) * PPAD + nt * 8 + 2 * tig) = b;
        }
        rs0 += __shfl_xor_sync(0xffffffffu, rs0, 1);
        rs0 += __shfl_xor_sync(0xffffffffu, rs0, 2);
        rs1 += __shfl_xor_sync(0xffffffffu, rs1, 1);
        rs1 += __shfl_xor_sync(0xffffffffu, rs1, 2);
        l0s = l0s * corr0 + rs0;
        l1s = l1s * corr1 + rs1;
        m0 = mn0; m1 = mn1;
#pragma unroll
        for (int nt = 0; nt < 8; nt++) {
            acc_o[nt][0] *= corr0; acc_o[nt][1] *= corr0;
            acc_o[nt][2] *= corr1; acc_o[nt][3] *= corr1;
        }
        __syncwarp();

#pragma unroll
        for (int ks = 0; ks < 8; ks++) {
            int kk = ks * 8 + tig;
            uint32_t pf[4];
            ldsm4(pf, pAddr + (uint32_t)(ks * 32));
#pragma unroll
            for (int nt = 0; nt < 8; nt++) {
                uint32_t vf[2];
                vf[0] = v_s[kk * KPV + nt * 8 + g];
                vf[1] = v_s[(kk + 4) * KPV + nt * 8 + g];
                mma_tf32(acc_o[nt], pf, vf);
            }
        }
        __syncwarp();
    }

    {
        float mf0 = fmaxf(m0, 0.f), mf1 = fmaxf(m1, 0.f);
        float c0 = __expf(m0 - mf0), c1 = __expf(m1 - mf1);
        float pw0 = __expf(-mf0), pw1 = __expf(-mf1);
        float lf0 = l0s * c0 + pw0, lf1 = l1s * c1 + pw1;
        float inv0 = 1.f / lf0, inv1 = 1.f / lf1;
        int r0 = l0 + wm + g, r1 = r0 + 8;
        const float* nb = noise + (n * H_ + h) * HD_;
        float* o0p = Out + ((size_t)r0 * N_ + n) * D_ + h * HD_;
        float* o1p = Out + ((size_t)r1 * N_ + n) * D_ + h * HD_;
#pragma unroll
        for (int nt = 0; nt < 8; nt++) {
            int col = nt * 8 + 2 * tig;
            float nv0 = nb[col], nv1 = nb[col + 1];
            *(float2*)(o0p + col) = make_float2(
                tf32round((acc_o[nt][0] * c0 + pw0 * nv0) * inv0),
                tf32round((acc_o[nt][1] * c0 + pw0 * nv1) * inv0));
            *(float2*)(o1p + col) = make_float2(
                tf32round((acc_o[nt][2] * c1 + pw1 * nv0) * inv1),
                tf32round((acc_o[nt][3] * c1 + pw1 * nv1) * inv1));
        }
        if (tig == 0) {
            size_t base = (size_t)(n * H_ + h) * L_;
            Mb[base + r0] = mf0; Zb[base + r0] = lf0;
            Mb[base + r1] = mf1; Zb[base + r1] = lf1;
        }
    }
}

// ---------------- tensor-core attn_map (ldmatrix frags) ----------------
#define AMQ 68
#define AMK 68
#define ATTNMAP_SMEM ((128*AMQ + 64*AMK)*4)
__global__ void __launch_bounds__(256) attnmap_kernel(
    const float* __restrict__ Q, const float* __restrict__ Kb,
    const float* __restrict__ Mb, const float* __restrict__ Zb,
    float* __restrict__ Out2) {
    extern __shared__ uint32_t su[];
    uint32_t* q_s = su;
    uint32_t* k_s = su + 128 * AMQ;
    const uint32_t smem_u32 = (uint32_t)__cvta_generic_to_shared(su);
    const int n = blockIdx.z, l0 = blockIdx.x * 128, s0 = blockIdx.y * 64;
    const int tid = threadIdx.x;
    const int warp = tid >> 5, lane = tid & 31;
    const int g = lane >> 2, tig = lane & 3;
    const int wm = warp * 16;

    const int arow = ((lane >> 3) & 1) * 8 + (lane & 7);
    const uint32_t akb = ((lane >> 4) & 1) * 16;
    const int brow = ((lane >> 4) & 1) * 8 + (lane & 7);
    const uint32_t bkb = ((lane >> 3) & 1) * 16;
    const uint32_t qAddr = smem_u32 + (uint32_t)((wm + arow) * AMQ * 4) + akb;
    const uint32_t kAddr = smem_u32 + (uint32_t)(128 * AMQ * 4)
                         + (uint32_t)(brow * AMK * 4) + bkb;

    float acc[8][4];
#pragma unroll
    for (int nt = 0; nt < 8; nt++)
#pragma unroll
        for (int j = 0; j < 4; j++) acc[nt][j] = 0.f;

    for (int h = 0; h < H_; h++) {
        __syncthreads();
        for (int t = tid; t < 128 * 16; t += 256) {
            int r = t >> 4, dc = (t & 15) << 2;
            *(uint4*)(q_s + r * AMQ + dc) =
                *(const uint4*)(Q + ((size_t)(l0 + r) * N_ + n) * D_ + h * HD_ + dc);
        }
        for (int t = tid; t < 64 * 16; t += 256) {
            int s = t >> 4, dc = (t & 15) << 2;
            *(uint4*)(k_s + s * AMK + dc) =
                *(const uint4*)(Kb + ((size_t)(s0 + s) * N_ + n) * D_ + h * HD_ + dc);
        }
        __syncthreads();

        float s_[8][4];
#pragma unroll
        for (int nt = 0; nt < 8; nt++)
#pragma unroll
            for (int j = 0; j < 4; j++) s_[nt][j] = 0.f;
#pragma unroll
        for (int ks = 0; ks < 8; ks++) {
            uint32_t koff = (uint32_t)(ks * 32);
            uint32_t qfr[4];
            ldsm4(qfr, qAddr + koff);
#pragma unroll
            for (int p = 0; p < 4; p++) {
                uint32_t r[4];
                ldsm4(r, kAddr + (uint32_t)(p * 16 * AMK * 4) + koff);
                uint32_t kf0[2] = {r[0], r[1]};
                uint32_t kf1[2] = {r[2], r[3]};
                mma_tf32(s_[2 * p], qfr, kf0);
                mma_tf32(s_[2 * p + 1], qfr, kf1);
            }
        }

        size_t mz = (size_t)(n * H_ + h) * L_;
        int r0 = l0 + wm + g, r1 = r0 + 8;
        float mf0 = Mb[mz + r0], iz0 = 1.f / Zb[mz + r0];
        float mf1 = Mb[mz + r1], iz1 = 1.f / Zb[mz + r1];
#pragma unroll
        for (int nt = 0; nt < 8; nt++) {
            float w00 = __expf(s_[nt][0] - mf0) * iz0;
            float w01 = __expf(s_[nt][1] - mf0) * iz0;
            float w10 = __expf(s_[nt][2] - mf1) * iz1;
            float w11 = __expf(s_[nt][3] - mf1) * iz1;
            acc[nt][0] += __fdividef(1.f, 1.f + __expf(-w00));
            acc[nt][1] += __fdividef(1.f, 1.f + __expf(-w01));
            acc[nt][2] += __fdividef(1.f, 1.f + __expf(-w10));
            acc[nt][3] += __fdividef(1.f, 1.f + __expf(-w11));
        }
    }

    int r0 = l0 + wm + g, r1 = r0 + 8;
#pragma unroll
    for (int nt = 0; nt < 8; nt++) {
        int col = s0 + nt * 8 + 2 * tig;
        *(float2*)(Out2 + ((size_t)n * L_ + r0) * S_ + col) =
            make_float2(acc[nt][0] * (1.f / 16.f), acc[nt][1] * (1.f / 16.f));
        *(float2*)(Out2 + ((size_t)n * L_ + r1) * S_ + col) =
            make_float2(acc[nt][2] * (1.f / 16.f), acc[nt][3] * (1.f / 16.f));
    }
}

// ---------------- layernorm ----------------
__global__ void __launch_bounds__(256) ln_kernel(
    const float* __restrict__ X, const float* __restrict__ g,
    const float* __restrict__ b, float* __restrict__ Y) {
    const int row = blockIdx.x;
    const int tid = threadIdx.x;
    const float* x = X + (size_t)row * D_;
    float4 v = *(const float4*)(x + tid * 4);
    __shared__ float red[8];
    const int wid = tid >> 5, lane = tid & 31;

    float s = v.x + v.y + v.z + v.w;
#pragma unroll
    for (int o = 16; o; o >>= 1) s += __shfl_xor_sync(0xffffffffu, s, o);
    if (!lane) red[wid] = s;
    __syncthreads();
    float tot = 0.f;
#pragma unroll
    for (int w = 0; w < 8; w++) tot += red[w];
    float mean = tot * (1.f / D_);

    float dx = v.x - mean, dy = v.y - mean, dz = v.z - mean, dw = v.w - mean;
    float ss = dx * dx + dy * dy + dz * dz + dw * dw;
#pragma unroll
    for (int o = 16; o; o >>= 1) ss += __shfl_xor_sync(0xffffffffu, ss, o);
    __syncthreads();
    if (!lane) red[wid] = ss;
    __syncthreads();
    float tss = 0.f;
#pragma unroll
    for (int w = 0; w < 8; w++) tss += red[w];
    float inv = rsqrtf(tss * (1.f / D_) + 1e-5f);

    const int c = tid * 4;
    float4 gv = *(const float4*)(g + c);
    float4 bv = *(const float4*)(b + c);
    float4 o;
    o.x = dx * inv * gv.x + bv.x;
    o.y = dy * inv * gv.y + bv.y;
    o.z = dz * inv * gv.z + bv.z;
    o.w = dw * inv * gv.w + bv.w;
    *(float4*)(Y + (size_t)row * D_ + c) = o;
}

// ---------------- orchestration ----------------
extern "C" void kernel_launch(void* const* d_in, const int* in_sizes, int n_in,
                              void* d_out, int out_size) {
    const float* key_in   = (const float*)d_in[0];
    const float* value_in = (const float*)d_in[1];
    const float* query    = (const float*)d_in[2];
    const float* ipw      = (const float*)d_in[3];
    const float* ipb      = (const float*)d_in[4];
    const float* ow       = (const float*)d_in[5];
    const float* ob       = (const float*)d_in[6];
    const float* ln1g     = (const float*)d_in[7];
    const float* ln1b     = (const float*)d_in[8];
    const float* ln2g     = (const float*)d_in[9];
    const float* ln2b     = (const float*)d_in[10];
    const float* f1w      = (const float*)d_in[11];
    const float* f1b      = (const float*)d_in[12];
    const float* f2w      = (const float*)d_in[13];
    const float* f2b      = (const float*)d_in[14];
    float* out = (float*)d_out;

    float *qb, *kb, *vb, *ab, *tb, *xb, *fb, *gb, *Mb, *Zb, *nz, *wt;
    cudaGetSymbolAddress((void**)&qb, g_q);
    cudaGetSymbolAddress((void**)&kb, g_k);
    cudaGetSymbolAddress((void**)&vb, g_v);
    cudaGetSymbolAddress((void**)&ab, g_attn);
    cudaGetSymbolAddress((void**)&tb, g_tmp);
    cudaGetSymbolAddress((void**)&xb, g_x);
    cudaGetSymbolAddress((void**)&fb, g_ff);
    cudaGetSymbolAddress((void**)&gb, g_tgt);
    cudaGetSymbolAddress((void**)&Mb, g_M);
    cudaGetSymbolAddress((void**)&Zb, g_Z);
    cudaGetSymbolAddress((void**)&nz, g_noise);
    cudaGetSymbolAddress((void**)&wt, g_wtf);

    float* wqkv = wt;
    float* wout = wqkv + 6291456;
    float* wf1  = wout + 2097152;
    float* wf2  = wf1  + 8388608;

    cudaFuncSetAttribute(tgemm_kernel<false, true, false, false>, cudaFuncAttributeMaxDynamicSharedMemorySize, TGEMM_SMEM);
    cudaFuncSetAttribute(tgemm_kernel<true, false, true, true>,   cudaFuncAttributeMaxDynamicSharedMemorySize, TGEMM_SMEM);
    cudaFuncSetAttribute(qkv_kernel, cudaFuncAttributeMaxDynamicSharedMemorySize, TGEMM_SMEM);
    cudaFuncSetAttribute(attn_kernel, cudaFuncAttributeMaxDynamicSharedMemorySize, ATTN_SMEM);
    cudaFuncSetAttribute(attnmap_kernel, cudaFuncAttributeMaxDynamicSharedMemorySize, ATTNMAP_SMEM);

    noise_kernel<<<16, 256>>>(nz);
    wcvt_all_kernel<<<6291456 / 256, 256>>>(ipw, ow, f1w, f2w, wt);

    for (int i = 0; i < 2; i++) {
        const float* xin = i ? gb : query;
        const float* W   = wqkv + (size_t)i * 3 * D_ * D_;
        const float* Bi  = ipb + (size_t)i * 3 * D_;

        qkv_kernel<<<dim3(8, 96), 256, TGEMM_SMEM>>>(xin, key_in, value_in, W, Bi, qb, kb, vb);

        attn_kernel<<<dim3(L_ / QROWS, H_, N_), 512, ATTN_SMEM>>>(qb, kb, vb, nz + i * 2048, ab, Mb, Zb);

        tgemm_kernel<false, true, false, false><<<dim3(8, 64), 256, TGEMM_SMEM>>>(
            ab, wout + (size_t)i * D_ * D_, ob + i * D_, tb, xin, ML, D_, D_, 1.f);
        ln_kernel<<<ML, 256>>>(tb, ln1g + i * D_, ln1b + i * D_, xb);

        tgemm_kernel<true, false, true, true><<<dim3(32, 64), 256, TGEMM_SMEM>>>(
            xb, wf1 + (size_t)i * FF_ * D_, f1b + i * FF_, fb, nullptr, ML, FF_, D_, 1.f);
        tgemm_kernel<false, true, false, false><<<dim3(8, 64), 256, TGEMM_SMEM>>>(
            fb, wf2 + (size_t)i * D_ * FF_, f2b + i * D_, tb, xb, ML, D_, FF_, 1.f);
        ln_kernel<<<ML, 256>>>(tb, ln2g + i * D_, ln2b + i * D_, i ? out : gb);
    }

    attnmap_kernel<<<dim3(L_ / 128, S_ / 64, N_), 256, ATTNMAP_SMEM>>>(qb, kb, Mb, Zb, out + (size_t)ML * D_);
}